// round 1
// baseline (speedup 1.0000x reference)
#include <cuda_runtime.h>
#include <math_constants.h>

#define S_LEN  2048
#define HIDDEN 4096
#define NH     32
#define NKV    8
#define HD     96
#define GROUPS 4
#define QDIM   (NH * HD)    // 3072
#define KVDIM  (NKV * HD)   // 768
#define DFULL  128
#define ATT_SCALE 0.08838834764831845f  // 128^-0.5

// ---------------- scratch (allocation-free: device globals) ----------------
static __device__ float g_Q [S_LEN * QDIM];
static __device__ float g_K [S_LEN * KVDIM];
static __device__ float g_V [S_LEN * KVDIM];
static __device__ float g_AO[S_LEN * QDIM];

// ---------------------------------------------------------------------------
// Generic fp32 GEMM:  C[M,N] = A[M,K] * B[N,K]^T   (both row-major)
// Tile 128x128, BK=8, 256 threads, 8x8 accumulators per thread.
// Requires M%128==0, N%128==0, K%8==0 (true for every call here).
// ---------------------------------------------------------------------------
__global__ __launch_bounds__(256) void sgemm_tn(
    const float* __restrict__ A, const float* __restrict__ B,
    float* __restrict__ C, int M, int N, int K)
{
    __shared__ float As[8][128];
    __shared__ float Bs[8][128];

    const int bm  = blockIdx.y * 128;
    const int bn  = blockIdx.x * 128;
    const int tid = threadIdx.x;

    // global-load mapping: 256 threads fetch one float4 each of A-tile and B-tile
    const int lrow = tid >> 1;          // 0..127
    const int lcol = (tid & 1) << 2;    // 0 or 4
    const float* Ap = A + (size_t)(bm + lrow) * K + lcol;
    const float* Bp = B + (size_t)(bn + lrow) * K + lcol;

    const int tx = tid & 15;            // 16x16 thread grid
    const int ty = tid >> 4;

    float acc[8][8];
#pragma unroll
    for (int i = 0; i < 8; i++)
#pragma unroll
        for (int j = 0; j < 8; j++) acc[i][j] = 0.f;

    for (int k0 = 0; k0 < K; k0 += 8) {
        float4 a = *(const float4*)(Ap + k0);
        float4 b = *(const float4*)(Bp + k0);
        __syncthreads();   // previous tile fully consumed
        As[lcol + 0][lrow] = a.x; As[lcol + 1][lrow] = a.y;
        As[lcol + 2][lrow] = a.z; As[lcol + 3][lrow] = a.w;
        Bs[lcol + 0][lrow] = b.x; Bs[lcol + 1][lrow] = b.y;
        Bs[lcol + 2][lrow] = b.z; Bs[lcol + 3][lrow] = b.w;
        __syncthreads();

#pragma unroll
        for (int k = 0; k < 8; k++) {
            float ar[8], br[8];
            *(float4*)&ar[0] = *(const float4*)&As[k][ty * 8];
            *(float4*)&ar[4] = *(const float4*)&As[k][ty * 8 + 4];
            *(float4*)&br[0] = *(const float4*)&Bs[k][tx * 8];
            *(float4*)&br[4] = *(const float4*)&Bs[k][tx * 8 + 4];
#pragma unroll
            for (int i = 0; i < 8; i++)
#pragma unroll
                for (int j = 0; j < 8; j++)
                    acc[i][j] = fmaf(ar[i], br[j], acc[i][j]);
        }
    }

#pragma unroll
    for (int i = 0; i < 8; i++) {
        float* Cp = C + (size_t)(bm + ty * 8 + i) * N + bn + tx * 8;
        *(float4*)(Cp + 0) = make_float4(acc[i][0], acc[i][1], acc[i][2], acc[i][3]);
        *(float4*)(Cp + 4) = make_float4(acc[i][4], acc[i][5], acc[i][6], acc[i][7]);
    }
}

// ---------------------------------------------------------------------------
// Indexed RoPE, in place. X layout: [S, nheads*HD]. One thread per (s,h,d<48)
// pair; handles both halves of the rotate.
// ---------------------------------------------------------------------------
__global__ void rope_kernel(float* __restrict__ X,
                            const float* __restrict__ cosT,
                            const float* __restrict__ sinT,
                            const int* __restrict__ idx,
                            int nheads, int group, int total)
{
    int t = blockIdx.x * blockDim.x + threadIdx.x;
    if (t >= total) return;
    int d = t % 48;
    int h = (t / 48) % nheads;
    int s = t / (48 * nheads);
    int hk = h / group;

    float* base = X + (size_t)s * (nheads * HD) + h * HD;
    float x1 = base[d];
    float x2 = base[d + 48];

    int i1 = idx[hk * HD + d];
    int i2 = idx[hk * HD + d + 48];
    float c1 = cosT[s * DFULL + i1], s1 = sinT[s * DFULL + i1];
    float c2 = cosT[s * DFULL + i2], s2 = sinT[s * DFULL + i2];

    base[d]      = x1 * c1 - x2 * s1;   // out_lo = x1*cos + (-x2)*sin
    base[d + 48] = x2 * c2 + x1 * s2;   // out_hi = x2*cos + ( x1)*sin
}

// ---------------------------------------------------------------------------
// Causal GQA flash attention, fp32. One warp per query row, 8 rows per CTA.
// 32-key tiles staged transposed in smem (conflict-free reads); online softmax.
// ---------------------------------------------------------------------------
__global__ __launch_bounds__(256) void flash_kernel(
    const float* __restrict__ Q, const float* __restrict__ K,
    const float* __restrict__ V, float* __restrict__ O)
{
    __shared__ float kT[HD][33];
    __shared__ float vT[HD][33];

    const int h     = blockIdx.y;
    const int hk    = h / GROUPS;
    const int qbase = blockIdx.x * 8;
    const int w     = threadIdx.x >> 5;
    const int lane  = threadIdx.x & 31;
    const int qr    = qbase + w;

    const float* qp = Q + (size_t)qr * QDIM + h * HD;
    float q0 = qp[lane], q1 = qp[lane + 32], q2 = qp[lane + 64];

    float m = -CUDART_INF_F, l = 0.f;
    float o0 = 0.f, o1 = 0.f, o2 = 0.f;

    const int nb = (qbase + 8 + 31) >> 5;  // key blocks covering rows qbase..qbase+7
    for (int kb = 0; kb < nb; kb++) {
        __syncthreads();
        for (int i = threadIdx.x; i < 32 * HD; i += 256) {
            int j = i / HD, d = i - j * HD;
            int key = (kb << 5) + j;
            kT[d][j] = K[(size_t)key * KVDIM + hk * HD + d];
            vT[d][j] = V[(size_t)key * KVDIM + hk * HD + d];
        }
        __syncthreads();

        const int key0 = kb << 5;
        if (key0 <= qr) {
            // 32 scores in parallel: lane owns key = key0 + lane
            float s = 0.f;
#pragma unroll
            for (int d = 0; d < 32; d++)
                s = fmaf(__shfl_sync(0xffffffffu, q0, d), kT[d][lane], s);
#pragma unroll
            for (int d = 0; d < 32; d++)
                s = fmaf(__shfl_sync(0xffffffffu, q1, d), kT[d + 32][lane], s);
#pragma unroll
            for (int d = 0; d < 32; d++)
                s = fmaf(__shfl_sync(0xffffffffu, q2, d), kT[d + 64][lane], s);
            s *= ATT_SCALE;
            if (key0 + lane > qr) s = -CUDART_INF_F;   // causal mask

            float mx = s;
#pragma unroll
            for (int off = 16; off; off >>= 1)
                mx = fmaxf(mx, __shfl_xor_sync(0xffffffffu, mx, off));
            float mnew  = fmaxf(m, mx);                // finite: key0<=qr ensures a valid key
            float alpha = __expf(m - mnew);            // m==-inf -> 0 (first block)
            float p     = __expf(s - mnew);            // masked -> 0
            float ps = p;
#pragma unroll
            for (int off = 16; off; off >>= 1)
                ps += __shfl_xor_sync(0xffffffffu, ps, off);
            l = l * alpha + ps;
            m = mnew;
            o0 *= alpha; o1 *= alpha; o2 *= alpha;
#pragma unroll
            for (int j = 0; j < 32; j++) {
                float pj = __shfl_sync(0xffffffffu, p, j);
                o0 = fmaf(pj, vT[lane][j],      o0);
                o1 = fmaf(pj, vT[lane + 32][j], o1);
                o2 = fmaf(pj, vT[lane + 64][j], o2);
            }
        }
    }

    float inv = 1.0f / l;
    float* op = O + (size_t)qr * QDIM + h * HD;
    op[lane]      = o0 * inv;
    op[lane + 32] = o1 * inv;
    op[lane + 64] = o2 * inv;
}

// ---------------------------------------------------------------------------
extern "C" void kernel_launch(void* const* d_in, const int* in_sizes, int n_in,
                              void* d_out, int out_size)
{
    const float* hs  = (const float*)d_in[0];
    const float* cs  = (const float*)d_in[1];
    const float* sn  = (const float*)d_in[2];
    const int*   idx = (const int*)  d_in[3];
    const float* Wq  = (const float*)d_in[4];
    const float* Wk  = (const float*)d_in[5];
    const float* Wv  = (const float*)d_in[6];
    const float* Wo  = (const float*)d_in[7];
    float* out = (float*)d_out;

    float *Qb, *Kb, *Vb, *AOb;
    cudaGetSymbolAddress((void**)&Qb,  g_Q);
    cudaGetSymbolAddress((void**)&Kb,  g_K);
    cudaGetSymbolAddress((void**)&Vb,  g_V);
    cudaGetSymbolAddress((void**)&AOb, g_AO);

    // QKV projections
    sgemm_tn<<<dim3(QDIM / 128,  S_LEN / 128), 256>>>(hs, Wq, Qb, S_LEN, QDIM,  HIDDEN);
    sgemm_tn<<<dim3(KVDIM / 128, S_LEN / 128), 256>>>(hs, Wk, Kb, S_LEN, KVDIM, HIDDEN);
    sgemm_tn<<<dim3(KVDIM / 128, S_LEN / 128), 256>>>(hs, Wv, Vb, S_LEN, KVDIM, HIDDEN);

    // indexed RoPE on Q and K
    const int totQ = S_LEN * NH  * 48;
    const int totK = S_LEN * NKV * 48;
    rope_kernel<<<(totQ + 255) / 256, 256>>>(Qb, cs, sn, idx, NH,  GROUPS, totQ);
    rope_kernel<<<(totK + 255) / 256, 256>>>(Kb, cs, sn, idx, NKV, 1,      totK);

    // causal GQA attention
    flash_kernel<<<dim3(S_LEN / 8, NH), 256>>>(Qb, Kb, Vb, AOb);

    // output projection -> d_out
    sgemm_tn<<<dim3(HIDDEN / 128, S_LEN / 128), 256>>>(AOb, Wo, out, S_LEN, HIDDEN, QDIM);
}

// round 3
// speedup vs baseline: 1.7115x; 1.7115x over previous
#include <cuda_runtime.h>
#include <cuda_bf16.h>
#include <math_constants.h>
#include <cstdint>

#define S_LEN  2048
#define HIDDEN 4096
#define NH     32
#define NKV    8
#define HD     96
#define GROUPS 4
#define QDIM   (NH * HD)    // 3072
#define KVDIM  (NKV * HD)   // 768
#define DFULL  128
#define ATT_SCALE 0.08838834764831845f  // 128^-0.5

#define KP_QKV (3 * HIDDEN)   // 12288
#define KP_O   (3 * QDIM)     // 9216

// ---------------- scratch (allocation-free: device globals) ----------------
static __device__ __align__(256) float g_Q [S_LEN * QDIM];
static __device__ __align__(256) float g_K [S_LEN * KVDIM];
static __device__ __align__(256) float g_V [S_LEN * KVDIM];
static __device__ __align__(256) float g_AO[S_LEN * QDIM];

static __device__ __align__(256) __nv_bfloat16 g_hsb[S_LEN * KP_QKV];   // [Ah|Al|Ah]
static __device__ __align__(256) __nv_bfloat16 g_wqb[QDIM * KP_QKV];    // [Bh|Bh|Bl]
static __device__ __align__(256) __nv_bfloat16 g_wkb[KVDIM * KP_QKV];
static __device__ __align__(256) __nv_bfloat16 g_wvb[KVDIM * KP_QKV];
static __device__ __align__(256) __nv_bfloat16 g_aob[S_LEN * KP_O];
static __device__ __align__(256) __nv_bfloat16 g_wob[HIDDEN * KP_O];

// ---------------------------------------------------------------------------
// PTX helpers (mma.sync / ldmatrix / cp.async — all legal on compute_103 base)
// ---------------------------------------------------------------------------
__device__ __forceinline__ uint32_t smem_u32(const void* p) {
    uint32_t a;
    asm("{ .reg .u64 t; cvta.to.shared.u64 t, %1; cvt.u32.u64 %0, t; }" : "=r"(a) : "l"(p));
    return a;
}
#define CP_ASYNC16(dst, src) asm volatile("cp.async.cg.shared.global [%0], [%1], 16;" :: "r"(dst), "l"(src))
#define CP_COMMIT()          asm volatile("cp.async.commit_group;" ::: "memory")
#define CP_WAIT(n)           asm volatile("cp.async.wait_group %0;" :: "n"(n) : "memory")

#define LDSM_X4(r0, r1, r2, r3, addr)                                            \
    asm volatile("ldmatrix.sync.aligned.m8n8.x4.shared.b16 {%0,%1,%2,%3}, [%4];" \
        : "=r"(r0), "=r"(r1), "=r"(r2), "=r"(r3) : "r"(addr))

__device__ __forceinline__ void mma_bf16(float* c, uint32_t a0, uint32_t a1,
                                         uint32_t a2, uint32_t a3,
                                         uint32_t b0, uint32_t b1) {
    asm volatile(
        "mma.sync.aligned.m16n8k16.row.col.f32.bf16.bf16.f32 "
        "{%0,%1,%2,%3}, {%4,%5,%6,%7}, {%8,%9}, {%0,%1,%2,%3};"
        : "+f"(c[0]), "+f"(c[1]), "+f"(c[2]), "+f"(c[3])
        : "r"(a0), "r"(a1), "r"(a2), "r"(a3), "r"(b0), "r"(b1));
}

// ---------------------------------------------------------------------------
// bf16 HMMA GEMM:  C[M,N] = A[M,Kp] * B[N,Kp]^T   (bf16 in, fp32 accum/out)
// BM=128, BN=128, BK=64. 8 warps (4m x 2n), warp tile 32x64.
// Smem rows have 144-byte stride (BK*2 + 16) -> conflict-free ldmatrix.
// ---------------------------------------------------------------------------
#define BM 128
#define BN 128
#define BKE 64
#define ROW_B 144                         // bytes per smem row
#define TILE_BYTES (128 * ROW_B)          // 18432 per matrix
#define STAGE_BYTES (2 * TILE_BYTES)      // A + B
#define GEMM_SMEM (2 * STAGE_BYTES)       // double buffered = 73728

__device__ __forceinline__ void load_tiles(uint32_t sA, uint32_t sB,
    const __nv_bfloat16* __restrict__ A, const __nv_bfloat16* __restrict__ B,
    int bm, int bn, int kc, int Kp, int tid)
{
    const char* Ag = (const char*)(A + (size_t)bm * Kp + kc * BKE);
    const char* Bg = (const char*)(B + (size_t)bn * Kp + kc * BKE);
    const size_t rowb = (size_t)Kp * 2;
#pragma unroll
    for (int i = 0; i < 4; i++) {         // 128 rows x 8 segs of 16B, 256 threads
        int idx = tid + i * 256;
        int row = idx >> 3, seg = idx & 7;
        CP_ASYNC16(sA + row * ROW_B + seg * 16, Ag + (size_t)row * rowb + seg * 16);
    }
#pragma unroll
    for (int i = 0; i < 4; i++) {
        int idx = tid + i * 256;
        int row = idx >> 3, seg = idx & 7;
        CP_ASYNC16(sB + row * ROW_B + seg * 16, Bg + (size_t)row * rowb + seg * 16);
    }
}

__global__ __launch_bounds__(256) void gemm_mma(
    const __nv_bfloat16* __restrict__ A, const __nv_bfloat16* __restrict__ B,
    float* __restrict__ C, int M, int N, int Kp)
{
    extern __shared__ char smem[];
    const uint32_t sbase = smem_u32(smem);
    const int tid  = threadIdx.x;
    const int wid  = tid >> 5;
    const int lane = tid & 31;
    const int bm   = blockIdx.y * BM;
    const int bn   = blockIdx.x * BN;
    const int wm   = (wid >> 1) * 32;     // warp m offset in tile
    const int wn   = (wid & 1) * 64;      // warp n offset in tile
    const int NC   = Kp / BKE;

    float acc[2][8][4];
#pragma unroll
    for (int t = 0; t < 2; t++)
#pragma unroll
        for (int j = 0; j < 8; j++)
#pragma unroll
            for (int q = 0; q < 4; q++) acc[t][j][q] = 0.f;

    // lane sub-addresses for ldmatrix x4 groups
    const int a_row = ((lane >> 3) & 1) * 8 + (lane & 7);   // + group2 col shift
    const int a_cshift = ((lane >> 4) & 1) * 16;
    const int b_row = ((lane >> 4) & 1) * 8 + (lane & 7);
    const int b_cshift = ((lane >> 3) & 1) * 16;

    load_tiles(sbase, sbase + TILE_BYTES, A, B, bm, bn, 0, Kp, tid);
    CP_COMMIT();

    for (int c = 0; c < NC; c++) {
        const int cur = c & 1;
        if (c + 1 < NC) {
            const int nxt = cur ^ 1;
            load_tiles(sbase + nxt * STAGE_BYTES, sbase + nxt * STAGE_BYTES + TILE_BYTES,
                       A, B, bm, bn, c + 1, Kp, tid);
            CP_COMMIT();
            CP_WAIT(1);
        } else {
            CP_WAIT(0);
        }
        __syncthreads();

        const uint32_t sA = sbase + cur * STAGE_BYTES;
        const uint32_t sB = sA + TILE_BYTES;
#pragma unroll
        for (int ks = 0; ks < 4; ks++) {
            uint32_t a[2][4];
#pragma unroll
            for (int t = 0; t < 2; t++) {
                uint32_t addr = sA + (wm + t * 16 + a_row) * ROW_B + ks * 32 + a_cshift;
                LDSM_X4(a[t][0], a[t][1], a[t][2], a[t][3], addr);
            }
#pragma unroll
            for (int p = 0; p < 4; p++) {
                uint32_t b0, b1, b2, b3;
                uint32_t addr = sB + (wn + p * 16 + b_row) * ROW_B + ks * 32 + b_cshift;
                LDSM_X4(b0, b1, b2, b3, addr);
#pragma unroll
                for (int t = 0; t < 2; t++) {
                    mma_bf16(acc[t][2 * p],     a[t][0], a[t][1], a[t][2], a[t][3], b0, b1);
                    mma_bf16(acc[t][2 * p + 1], a[t][0], a[t][1], a[t][2], a[t][3], b2, b3);
                }
            }
        }
        __syncthreads();
    }

    // epilogue: fp32 stores (fragment: c0,c1 row=lane/4 col=2*(lane%4); c2,c3 row+8)
#pragma unroll
    for (int t = 0; t < 2; t++) {
        const int r0 = bm + wm + t * 16 + (lane >> 2);
#pragma unroll
        for (int j = 0; j < 8; j++) {
            const int col = bn + wn + j * 8 + (lane & 3) * 2;
            float* c0 = C + (size_t)r0 * N + col;
            float* c1 = C + (size_t)(r0 + 8) * N + col;
            *(float2*)c0 = make_float2(acc[t][j][0], acc[t][j][1]);
            *(float2*)c1 = make_float2(acc[t][j][2], acc[t][j][3]);
        }
    }
}

// ---------------------------------------------------------------------------
// fp32 -> split bf16. mode 0 (A side): [hi | lo | hi]; mode 1 (B side): [hi | hi | lo]
// ---------------------------------------------------------------------------
__global__ void split_kernel(const float* __restrict__ X, __nv_bfloat16* __restrict__ Y,
                             int total, int C, int mode)
{
    int t = blockIdx.x * blockDim.x + threadIdx.x;
    if (t >= total) return;
    int r = t / C, c = t - r * C;
    float x = X[t];
    __nv_bfloat16 h = __float2bfloat16(x);
    __nv_bfloat16 l = __float2bfloat16(x - __bfloat162float(h));
    __nv_bfloat16* row = Y + (size_t)r * 3 * C;
    if (mode == 0) { row[c] = h; row[C + c] = l; row[2 * C + c] = h; }
    else           { row[c] = h; row[C + c] = h; row[2 * C + c] = l; }
}

// ---------------------------------------------------------------------------
// Indexed RoPE, in place. X layout: [S, nheads*HD].
// ---------------------------------------------------------------------------
__global__ void rope_kernel(float* __restrict__ X,
                            const float* __restrict__ cosT,
                            const float* __restrict__ sinT,
                            const int* __restrict__ idx,
                            int nheads, int group, int total)
{
    int t = blockIdx.x * blockDim.x + threadIdx.x;
    if (t >= total) return;
    int d = t % 48;
    int h = (t / 48) % nheads;
    int s = t / (48 * nheads);
    int hk = h / group;

    float* base = X + (size_t)s * (nheads * HD) + h * HD;
    float x1 = base[d];
    float x2 = base[d + 48];

    int i1 = idx[hk * HD + d];
    int i2 = idx[hk * HD + d + 48];
    float c1 = cosT[s * DFULL + i1], s1 = sinT[s * DFULL + i1];
    float c2 = cosT[s * DFULL + i2], s2 = sinT[s * DFULL + i2];

    base[d]      = x1 * c1 - x2 * s1;
    base[d + 48] = x2 * c2 + x1 * s2;
}

// ---------------------------------------------------------------------------
// Causal GQA flash attention, fp32. One warp per query row, 8 rows per CTA.
// ---------------------------------------------------------------------------
__global__ __launch_bounds__(256) void flash_kernel(
    const float* __restrict__ Q, const float* __restrict__ K,
    const float* __restrict__ V, float* __restrict__ O)
{
    __shared__ float kT[HD][33];
    __shared__ float vT[HD][33];

    const int h     = blockIdx.y;
    const int hk    = h / GROUPS;
    const int qbase = blockIdx.x * 8;
    const int w     = threadIdx.x >> 5;
    const int lane  = threadIdx.x & 31;
    const int qr    = qbase + w;

    const float* qp = Q + (size_t)qr * QDIM + h * HD;
    float q0 = qp[lane], q1 = qp[lane + 32], q2 = qp[lane + 64];

    float m = -CUDART_INF_F, l = 0.f;
    float o0 = 0.f, o1 = 0.f, o2 = 0.f;

    const int nb = (qbase + 8 + 31) >> 5;
    for (int kb = 0; kb < nb; kb++) {
        __syncthreads();
        for (int i = threadIdx.x; i < 32 * HD; i += 256) {
            int j = i / HD, d = i - j * HD;
            int key = (kb << 5) + j;
            kT[d][j] = K[(size_t)key * KVDIM + hk * HD + d];
            vT[d][j] = V[(size_t)key * KVDIM + hk * HD + d];
        }
        __syncthreads();

        const int key0 = kb << 5;
        if (key0 <= qr) {
            float s = 0.f;
#pragma unroll
            for (int d = 0; d < 32; d++)
                s = fmaf(__shfl_sync(0xffffffffu, q0, d), kT[d][lane], s);
#pragma unroll
            for (int d = 0; d < 32; d++)
                s = fmaf(__shfl_sync(0xffffffffu, q1, d), kT[d + 32][lane], s);
#pragma unroll
            for (int d = 0; d < 32; d++)
                s = fmaf(__shfl_sync(0xffffffffu, q2, d), kT[d + 64][lane], s);
            s *= ATT_SCALE;
            if (key0 + lane > qr) s = -CUDART_INF_F;

            float mx = s;
#pragma unroll
            for (int off = 16; off; off >>= 1)
                mx = fmaxf(mx, __shfl_xor_sync(0xffffffffu, mx, off));
            float mnew  = fmaxf(m, mx);
            float alpha = __expf(m - mnew);
            float p     = __expf(s - mnew);
            float ps = p;
#pragma unroll
            for (int off = 16; off; off >>= 1)
                ps += __shfl_xor_sync(0xffffffffu, ps, off);
            l = l * alpha + ps;
            m = mnew;
            o0 *= alpha; o1 *= alpha; o2 *= alpha;
#pragma unroll
            for (int j = 0; j < 32; j++) {
                float pj = __shfl_sync(0xffffffffu, p, j);
                o0 = fmaf(pj, vT[lane][j],      o0);
                o1 = fmaf(pj, vT[lane + 32][j], o1);
                o2 = fmaf(pj, vT[lane + 64][j], o2);
            }
        }
    }

    float inv = 1.0f / l;
    float* op = O + (size_t)qr * QDIM + h * HD;
    op[lane]      = o0 * inv;
    op[lane + 32] = o1 * inv;
    op[lane + 64] = o2 * inv;
}

// ---------------------------------------------------------------------------
extern "C" void kernel_launch(void* const* d_in, const int* in_sizes, int n_in,
                              void* d_out, int out_size)
{
    const float* hs  = (const float*)d_in[0];
    const float* cs  = (const float*)d_in[1];
    const float* sn  = (const float*)d_in[2];
    const int*   idx = (const int*)  d_in[3];
    const float* Wq  = (const float*)d_in[4];
    const float* Wk  = (const float*)d_in[5];
    const float* Wv  = (const float*)d_in[6];
    const float* Wo  = (const float*)d_in[7];
    float* out = (float*)d_out;

    float *Qb, *Kb, *Vb, *AOb;
    __nv_bfloat16 *hsb, *wqb, *wkb, *wvb, *aob, *wob;
    cudaGetSymbolAddress((void**)&Qb,  g_Q);
    cudaGetSymbolAddress((void**)&Kb,  g_K);
    cudaGetSymbolAddress((void**)&Vb,  g_V);
    cudaGetSymbolAddress((void**)&AOb, g_AO);
    cudaGetSymbolAddress((void**)&hsb, g_hsb);
    cudaGetSymbolAddress((void**)&wqb, g_wqb);
    cudaGetSymbolAddress((void**)&wkb, g_wkb);
    cudaGetSymbolAddress((void**)&wvb, g_wvb);
    cudaGetSymbolAddress((void**)&aob, g_aob);
    cudaGetSymbolAddress((void**)&wob, g_wob);

    static bool attr_set = false;
    if (!attr_set) {
        cudaFuncSetAttribute(gemm_mma, cudaFuncAttributeMaxDynamicSharedMemorySize, GEMM_SMEM);
        attr_set = true;
    }

    // split fp32 -> [hi|lo|hi] / [hi|hi|lo] bf16
    {
        int t;
        t = S_LEN * HIDDEN; split_kernel<<<(t + 255) / 256, 256>>>(hs, hsb, t, HIDDEN, 0);
        t = QDIM  * HIDDEN; split_kernel<<<(t + 255) / 256, 256>>>(Wq, wqb, t, HIDDEN, 1);
        t = KVDIM * HIDDEN; split_kernel<<<(t + 255) / 256, 256>>>(Wk, wkb, t, HIDDEN, 1);
        t = KVDIM * HIDDEN; split_kernel<<<(t + 255) / 256, 256>>>(Wv, wvb, t, HIDDEN, 1);
        t = HIDDEN * QDIM;  split_kernel<<<(t + 255) / 256, 256>>>(Wo, wob, t, QDIM,   1);
    }

    // QKV projections (HMMA tensor cores)
    gemm_mma<<<dim3(QDIM  / BN, S_LEN / BM), 256, GEMM_SMEM>>>(hsb, wqb, Qb, S_LEN, QDIM,  KP_QKV);
    gemm_mma<<<dim3(KVDIM / BN, S_LEN / BM), 256, GEMM_SMEM>>>(hsb, wkb, Kb, S_LEN, KVDIM, KP_QKV);
    gemm_mma<<<dim3(KVDIM / BN, S_LEN / BM), 256, GEMM_SMEM>>>(hsb, wvb, Vb, S_LEN, KVDIM, KP_QKV);

    // indexed RoPE on Q and K
    const int totQ = S_LEN * NH  * 48;
    const int totK = S_LEN * NKV * 48;
    rope_kernel<<<(totQ + 255) / 256, 256>>>(Qb, cs, sn, idx, NH,  GROUPS, totQ);
    rope_kernel<<<(totK + 255) / 256, 256>>>(Kb, cs, sn, idx, NKV, 1,      totK);

    // causal GQA attention
    flash_kernel<<<dim3(S_LEN / 8, NH), 256>>>(Qb, Kb, Vb, AOb);

    // split attention output, then output projection -> d_out
    {
        int t = S_LEN * QDIM;
        split_kernel<<<(t + 255) / 256, 256>>>(AOb, aob, t, QDIM, 0);
    }
    gemm_mma<<<dim3(HIDDEN / BN, S_LEN / BM), 256, GEMM_SMEM>>>(aob, wob, out, S_LEN, HIDDEN, KP_O);
}

// round 4
// speedup vs baseline: 1.8310x; 1.0698x over previous
#include <cuda_runtime.h>
#include <cuda_bf16.h>
#include <math_constants.h>
#include <cstdint>

#define S_LEN  2048
#define HIDDEN 4096
#define NH     32
#define NKV    8
#define HD     96
#define GROUPS 4
#define QDIM   (NH * HD)    // 3072
#define KVDIM  (NKV * HD)   // 768
#define DFULL  128
#define ATT_SCALE 0.08838834764831845f  // 128^-0.5

#define KP_QKV (3 * HIDDEN)   // 12288
#define KP_O   (3 * QDIM)     // 9216

// ---------------- scratch (allocation-free: device globals) ----------------
static __device__ __align__(256) float g_Q [S_LEN * QDIM];
static __device__ __align__(256) float g_K [S_LEN * KVDIM];
static __device__ __align__(256) float g_V [S_LEN * KVDIM];
static __device__ __align__(256) float g_AO[S_LEN * QDIM];

static __device__ __align__(256) __nv_bfloat16 g_hsb[S_LEN * KP_QKV];   // [Ah|Al|Ah]
static __device__ __align__(256) __nv_bfloat16 g_wqb[QDIM * KP_QKV];    // [Bh|Bh|Bl]
static __device__ __align__(256) __nv_bfloat16 g_wkb[KVDIM * KP_QKV];
static __device__ __align__(256) __nv_bfloat16 g_wvb[KVDIM * KP_QKV];
static __device__ __align__(256) __nv_bfloat16 g_aob[S_LEN * KP_O];
static __device__ __align__(256) __nv_bfloat16 g_wob[HIDDEN * KP_O];

// ---------------------------------------------------------------------------
// PTX helpers
// ---------------------------------------------------------------------------
__device__ __forceinline__ uint32_t smem_u32(const void* p) {
    uint32_t a;
    asm("{ .reg .u64 t; cvta.to.shared.u64 t, %1; cvt.u32.u64 %0, t; }" : "=r"(a) : "l"(p));
    return a;
}
#define CP_ASYNC16(dst, src) asm volatile("cp.async.cg.shared.global [%0], [%1], 16;" :: "r"(dst), "l"(src))
#define CP_COMMIT()          asm volatile("cp.async.commit_group;" ::: "memory")
#define CP_WAIT(n)           asm volatile("cp.async.wait_group %0;" :: "n"(n) : "memory")

#define LDSM_X4(r0, r1, r2, r3, addr)                                            \
    asm volatile("ldmatrix.sync.aligned.m8n8.x4.shared.b16 {%0,%1,%2,%3}, [%4];" \
        : "=r"(r0), "=r"(r1), "=r"(r2), "=r"(r3) : "r"(addr))

__device__ __forceinline__ void mma_bf16(float* c, uint32_t a0, uint32_t a1,
                                         uint32_t a2, uint32_t a3,
                                         uint32_t b0, uint32_t b1) {
    asm volatile(
        "mma.sync.aligned.m16n8k16.row.col.f32.bf16.bf16.f32 "
        "{%0,%1,%2,%3}, {%4,%5,%6,%7}, {%8,%9}, {%0,%1,%2,%3};"
        : "+f"(c[0]), "+f"(c[1]), "+f"(c[2]), "+f"(c[3])
        : "r"(a0), "r"(a1), "r"(a2), "r"(a3), "r"(b0), "r"(b1));
}

// ---------------------------------------------------------------------------
// bf16 HMMA GEMM, segmented over N (up to 3 B/C segments sharing A).
// BM=128, BN=128, BK=64, 3-stage cp.async pipeline, 4 warps, warp tile 64x64.
// ---------------------------------------------------------------------------
#define BM 128
#define BN 128
#define BKE 64
#define ROW_B 144                          // bytes per smem row (128 data + 16 pad)
#define TILE_BYTES (128 * ROW_B)           // 18432
#define STAGE_BYTES (2 * TILE_BYTES)       // 36864
#define NSTAGE 3
#define GEMM_SMEM (NSTAGE * STAGE_BYTES)   // 110592

__device__ __forceinline__ void load_tiles(uint32_t stage_base,
    const __nv_bfloat16* __restrict__ A, const __nv_bfloat16* __restrict__ B,
    int bm, int bn, int kc, int Kp, int tid)
{
    const char* Ag = (const char*)(A + (size_t)bm * Kp + kc * BKE);
    const char* Bg = (const char*)(B + (size_t)bn * Kp + kc * BKE);
    const size_t rowb = (size_t)Kp * 2;
    const uint32_t sA = stage_base;
    const uint32_t sB = stage_base + TILE_BYTES;
#pragma unroll
    for (int i = 0; i < 8; i++) {          // A: 128 rows x 8 segs x 16B, 128 threads
        int idx = tid + i * 128;
        int row = idx >> 3, seg = idx & 7;
        CP_ASYNC16(sA + row * ROW_B + seg * 16, Ag + (size_t)row * rowb + seg * 16);
    }
#pragma unroll
    for (int i = 0; i < 8; i++) {
        int idx = tid + i * 128;
        int row = idx >> 3, seg = idx & 7;
        CP_ASYNC16(sB + row * ROW_B + seg * 16, Bg + (size_t)row * rowb + seg * 16);
    }
}

__global__ __launch_bounds__(128) void gemm_mma(
    const __nv_bfloat16* __restrict__ A,
    const __nv_bfloat16* __restrict__ B0, float* __restrict__ C0, int nt0, int N0,
    const __nv_bfloat16* __restrict__ B1, float* __restrict__ C1, int nt1, int N1,
    const __nv_bfloat16* __restrict__ B2, float* __restrict__ C2, int N2,
    int Kp)
{
    extern __shared__ char smem[];
    const uint32_t sbase = smem_u32(smem);
    const int tid  = threadIdx.x;
    const int wid  = tid >> 5;
    const int lane = tid & 31;
    const int bm   = blockIdx.y * BM;
    const int NC   = Kp / BKE;

    // segment select
    int bnt = blockIdx.x;
    const __nv_bfloat16* B;
    float* C; int N;
    if (bnt < nt0)            { B = B0; C = C0; N = N0; }
    else if (bnt < nt0 + nt1) { B = B1; C = C1; N = N1; bnt -= nt0; }
    else                      { B = B2; C = C2; N = N2; bnt -= nt0 + nt1; }
    const int bn = bnt * BN;

    const int wm = (wid >> 1) * 64;   // 2x2 warp grid, 64x64 warp tile
    const int wn = (wid & 1) * 64;

    float acc[4][8][4];
#pragma unroll
    for (int t = 0; t < 4; t++)
#pragma unroll
        for (int j = 0; j < 8; j++)
#pragma unroll
            for (int q = 0; q < 4; q++) acc[t][j][q] = 0.f;

    const int a_row    = ((lane >> 3) & 1) * 8 + (lane & 7);
    const int a_cshift = ((lane >> 4) & 1) * 16;
    const int b_row    = ((lane >> 4) & 1) * 8 + (lane & 7);
    const int b_cshift = ((lane >> 3) & 1) * 16;

    // prologue: stages 0,1
    load_tiles(sbase,               A, B, bm, bn, 0, Kp, tid); CP_COMMIT();
    load_tiles(sbase + STAGE_BYTES, A, B, bm, bn, 1, Kp, tid); CP_COMMIT();

    for (int c = 0; c < NC; c++) {
        CP_WAIT(1);                  // group c complete
        __syncthreads();

        // prefetch stage c+2
        if (c + 2 < NC)
            load_tiles(sbase + ((c + 2) % NSTAGE) * STAGE_BYTES, A, B, bm, bn, c + 2, Kp, tid);
        CP_COMMIT();                 // one group per iteration keeps wait counts exact

        const uint32_t sA = sbase + (c % NSTAGE) * STAGE_BYTES;
        const uint32_t sB = sA + TILE_BYTES;
#pragma unroll
        for (int ks = 0; ks < 4; ks++) {
            uint32_t a[4][4];
#pragma unroll
            for (int t = 0; t < 4; t++) {
                uint32_t addr = sA + (wm + t * 16 + a_row) * ROW_B + ks * 32 + a_cshift;
                LDSM_X4(a[t][0], a[t][1], a[t][2], a[t][3], addr);
            }
#pragma unroll
            for (int p = 0; p < 4; p++) {
                uint32_t b0, b1, b2, b3;
                uint32_t addr = sB + (wn + p * 16 + b_row) * ROW_B + ks * 32 + b_cshift;
                LDSM_X4(b0, b1, b2, b3, addr);
#pragma unroll
                for (int t = 0; t < 4; t++) {
                    mma_bf16(acc[t][2 * p],     a[t][0], a[t][1], a[t][2], a[t][3], b0, b1);
                    mma_bf16(acc[t][2 * p + 1], a[t][0], a[t][1], a[t][2], a[t][3], b2, b3);
                }
            }
        }
    }

    // epilogue
#pragma unroll
    for (int t = 0; t < 4; t++) {
        const int r0 = bm + wm + t * 16 + (lane >> 2);
#pragma unroll
        for (int j = 0; j < 8; j++) {
            const int col = bn + wn + j * 8 + (lane & 3) * 2;
            float* c0 = C + (size_t)r0 * N + col;
            float* c1 = C + (size_t)(r0 + 8) * N + col;
            *(float2*)c0 = make_float2(acc[t][j][0], acc[t][j][1]);
            *(float2*)c1 = make_float2(acc[t][j][2], acc[t][j][3]);
        }
    }
}

// ---------------------------------------------------------------------------
// fp32 -> split bf16, 2 elements/thread (32-bit smem-free stores).
// mode 0 (A side): [hi | lo | hi]; mode 1 (B side): [hi | hi | lo]
// ---------------------------------------------------------------------------
__global__ void split_kernel(const float* __restrict__ X, __nv_bfloat16* __restrict__ Y,
                             int totalPairs, int Cpairs, int mode)
{
    int t = blockIdx.x * blockDim.x + threadIdx.x;
    if (t >= totalPairs) return;
    int r = t / Cpairs, c = t - r * Cpairs;
    float2 x = *(const float2*)(X + 2 * (size_t)t);
    __nv_bfloat162 h = __floats2bfloat162_rn(x.x, x.y);
    __nv_bfloat162 l = __floats2bfloat162_rn(x.x - __bfloat162float(h.x),
                                             x.y - __bfloat162float(h.y));
    uint32_t* row = (uint32_t*)(Y + (size_t)r * 6 * Cpairs);
    uint32_t hv = *(uint32_t*)&h, lv = *(uint32_t*)&l;
    if (mode == 0) { row[c] = hv; row[Cpairs + c] = lv; row[2 * Cpairs + c] = hv; }
    else           { row[c] = hv; row[Cpairs + c] = hv; row[2 * Cpairs + c] = lv; }
}

// ---------------------------------------------------------------------------
// Indexed RoPE, in place. X layout: [S, nheads*HD].
// ---------------------------------------------------------------------------
__global__ void rope_kernel(float* __restrict__ X,
                            const float* __restrict__ cosT,
                            const float* __restrict__ sinT,
                            const int* __restrict__ idx,
                            int nheads, int group, int total)
{
    int t = blockIdx.x * blockDim.x + threadIdx.x;
    if (t >= total) return;
    int d = t % 48;
    int h = (t / 48) % nheads;
    int s = t / (48 * nheads);
    int hk = h / group;

    float* base = X + (size_t)s * (nheads * HD) + h * HD;
    float x1 = base[d];
    float x2 = base[d + 48];

    int i1 = idx[hk * HD + d];
    int i2 = idx[hk * HD + d + 48];
    float c1 = cosT[s * DFULL + i1], s1 = sinT[s * DFULL + i1];
    float c2 = cosT[s * DFULL + i2], s2 = sinT[s * DFULL + i2];

    base[d]      = x1 * c1 - x2 * s1;
    base[d + 48] = x2 * c2 + x1 * s2;
}

// ---------------------------------------------------------------------------
// Causal GQA flash attention, fp32. One warp per query row, 8 rows per CTA.
// ---------------------------------------------------------------------------
__global__ __launch_bounds__(256) void flash_kernel(
    const float* __restrict__ Q, const float* __restrict__ K,
    const float* __restrict__ V, float* __restrict__ O)
{
    __shared__ float kT[HD][33];
    __shared__ float vT[HD][33];

    const int h     = blockIdx.y;
    const int hk    = h / GROUPS;
    const int qbase = blockIdx.x * 8;
    const int w     = threadIdx.x >> 5;
    const int lane  = threadIdx.x & 31;
    const int qr    = qbase + w;

    const float* qp = Q + (size_t)qr * QDIM + h * HD;
    float q0 = qp[lane], q1 = qp[lane + 32], q2 = qp[lane + 64];

    float m = -CUDART_INF_F, l = 0.f;
    float o0 = 0.f, o1 = 0.f, o2 = 0.f;

    const int nb = (qbase + 8 + 31) >> 5;
    for (int kb = 0; kb < nb; kb++) {
        __syncthreads();
        for (int i = threadIdx.x; i < 32 * HD; i += 256) {
            int j = i / HD, d = i - j * HD;
            int key = (kb << 5) + j;
            kT[d][j] = K[(size_t)key * KVDIM + hk * HD + d];
            vT[d][j] = V[(size_t)key * KVDIM + hk * HD + d];
        }
        __syncthreads();

        const int key0 = kb << 5;
        if (key0 <= qr) {
            float s = 0.f;
#pragma unroll
            for (int d = 0; d < 32; d++)
                s = fmaf(__shfl_sync(0xffffffffu, q0, d), kT[d][lane], s);
#pragma unroll
            for (int d = 0; d < 32; d++)
                s = fmaf(__shfl_sync(0xffffffffu, q1, d), kT[d + 32][lane], s);
#pragma unroll
            for (int d = 0; d < 32; d++)
                s = fmaf(__shfl_sync(0xffffffffu, q2, d), kT[d + 64][lane], s);
            s *= ATT_SCALE;
            if (key0 + lane > qr) s = -CUDART_INF_F;

            float mx = s;
#pragma unroll
            for (int off = 16; off; off >>= 1)
                mx = fmaxf(mx, __shfl_xor_sync(0xffffffffu, mx, off));
            float mnew  = fmaxf(m, mx);
            float alpha = __expf(m - mnew);
            float p     = __expf(s - mnew);
            float ps = p;
#pragma unroll
            for (int off = 16; off; off >>= 1)
                ps += __shfl_xor_sync(0xffffffffu, ps, off);
            l = l * alpha + ps;
            m = mnew;
            o0 *= alpha; o1 *= alpha; o2 *= alpha;
#pragma unroll
            for (int j = 0; j < 32; j++) {
                float pj = __shfl_sync(0xffffffffu, p, j);
                o0 = fmaf(pj, vT[lane][j],      o0);
                o1 = fmaf(pj, vT[lane + 32][j], o1);
                o2 = fmaf(pj, vT[lane + 64][j], o2);
            }
        }
    }

    float inv = 1.0f / l;
    float* op = O + (size_t)qr * QDIM + h * HD;
    op[lane]      = o0 * inv;
    op[lane + 32] = o1 * inv;
    op[lane + 64] = o2 * inv;
}

// ---------------------------------------------------------------------------
extern "C" void kernel_launch(void* const* d_in, const int* in_sizes, int n_in,
                              void* d_out, int out_size)
{
    const float* hs  = (const float*)d_in[0];
    const float* cs  = (const float*)d_in[1];
    const float* sn  = (const float*)d_in[2];
    const int*   idx = (const int*)  d_in[3];
    const float* Wq  = (const float*)d_in[4];
    const float* Wk  = (const float*)d_in[5];
    const float* Wv  = (const float*)d_in[6];
    const float* Wo  = (const float*)d_in[7];
    float* out = (float*)d_out;

    float *Qb, *Kb, *Vb, *AOb;
    __nv_bfloat16 *hsb, *wqb, *wkb, *wvb, *aob, *wob;
    cudaGetSymbolAddress((void**)&Qb,  g_Q);
    cudaGetSymbolAddress((void**)&Kb,  g_K);
    cudaGetSymbolAddress((void**)&Vb,  g_V);
    cudaGetSymbolAddress((void**)&AOb, g_AO);
    cudaGetSymbolAddress((void**)&hsb, g_hsb);
    cudaGetSymbolAddress((void**)&wqb, g_wqb);
    cudaGetSymbolAddress((void**)&wkb, g_wkb);
    cudaGetSymbolAddress((void**)&wvb, g_wvb);
    cudaGetSymbolAddress((void**)&aob, g_aob);
    cudaGetSymbolAddress((void**)&wob, g_wob);

    static bool attr_set = false;
    if (!attr_set) {
        cudaFuncSetAttribute(gemm_mma, cudaFuncAttributeMaxDynamicSharedMemorySize, GEMM_SMEM);
        attr_set = true;
    }

    // split fp32 -> [hi|lo|hi] / [hi|hi|lo] bf16 (pair-vectorized)
    {
        int t;
        t = S_LEN * HIDDEN / 2; split_kernel<<<(t + 255) / 256, 256>>>(hs, hsb, t, HIDDEN / 2, 0);
        t = QDIM  * HIDDEN / 2; split_kernel<<<(t + 255) / 256, 256>>>(Wq, wqb, t, HIDDEN / 2, 1);
        t = KVDIM * HIDDEN / 2; split_kernel<<<(t + 255) / 256, 256>>>(Wk, wkb, t, HIDDEN / 2, 1);
        t = KVDIM * HIDDEN / 2; split_kernel<<<(t + 255) / 256, 256>>>(Wv, wvb, t, HIDDEN / 2, 1);
        t = HIDDEN * QDIM  / 2; split_kernel<<<(t + 255) / 256, 256>>>(Wo, wob, t, QDIM / 2,   1);
    }

    // fused QKV projection: 24 + 6 + 6 N-tiles, shared A
    gemm_mma<<<dim3(36, S_LEN / BM), 128, GEMM_SMEM>>>(
        hsb,
        wqb, Qb, QDIM / BN,  QDIM,
        wkb, Kb, KVDIM / BN, KVDIM,
        wvb, Vb,             KVDIM,
        KP_QKV);

    // indexed RoPE on Q and K
    const int totQ = S_LEN * NH  * 48;
    const int totK = S_LEN * NKV * 48;
    rope_kernel<<<(totQ + 255) / 256, 256>>>(Qb, cs, sn, idx, NH,  GROUPS, totQ);
    rope_kernel<<<(totK + 255) / 256, 256>>>(Kb, cs, sn, idx, NKV, 1,      totK);

    // causal GQA attention
    flash_kernel<<<dim3(S_LEN / 8, NH), 256>>>(Qb, Kb, Vb, AOb);

    // split attention output, then output projection -> d_out
    {
        int t = S_LEN * QDIM / 2;
        split_kernel<<<(t + 255) / 256, 256>>>(AOb, aob, t, QDIM / 2, 0);
    }
    gemm_mma<<<dim3(HIDDEN / BN, S_LEN / BM), 128, GEMM_SMEM>>>(
        aob,
        wob, out, HIDDEN / BN, HIDDEN,
        wob, out, 0,           HIDDEN,
        wob, out,              HIDDEN,
        KP_O);
}

// round 5
// speedup vs baseline: 5.1867x; 2.8328x over previous
#include <cuda_runtime.h>
#include <cuda_bf16.h>
#include <math_constants.h>
#include <cstdint>

#define S_LEN  2048
#define HIDDEN 4096
#define NH     32
#define NKV    8
#define HD     96
#define GROUPS 4
#define QDIM   (NH * HD)    // 3072
#define KVDIM  (NKV * HD)   // 768
#define DFULL  128
#define ATT_SCALE 0.08838834764831845f  // 128^-0.5

#define KP_QKV (3 * HIDDEN)   // 12288
#define KP_O   (3 * QDIM)     // 9216

// ---------------- scratch (allocation-free: device globals) ----------------
static __device__ __align__(256) float g_Q [S_LEN * QDIM];
static __device__ __align__(256) float g_K [S_LEN * KVDIM];
static __device__ __align__(256) float g_V [S_LEN * KVDIM];
static __device__ __align__(256) float g_AO[S_LEN * QDIM];

static __device__ __align__(256) __nv_bfloat16 g_hsb[S_LEN * KP_QKV];   // [Ah|Al|Ah]
static __device__ __align__(256) __nv_bfloat16 g_wqb[QDIM * KP_QKV];    // [Bh|Bh|Bl]
static __device__ __align__(256) __nv_bfloat16 g_wkb[KVDIM * KP_QKV];
static __device__ __align__(256) __nv_bfloat16 g_wvb[KVDIM * KP_QKV];
static __device__ __align__(256) __nv_bfloat16 g_aob[S_LEN * KP_O];
static __device__ __align__(256) __nv_bfloat16 g_wob[HIDDEN * KP_O];

// flash operands (hi/lo bf16 splits)
static __device__ __align__(256) __nv_bfloat16 g_Qh[S_LEN * QDIM];
static __device__ __align__(256) __nv_bfloat16 g_Ql[S_LEN * QDIM];
static __device__ __align__(256) __nv_bfloat16 g_Kh[S_LEN * KVDIM];
static __device__ __align__(256) __nv_bfloat16 g_Kl[S_LEN * KVDIM];
static __device__ __align__(256) __nv_bfloat16 g_Vh[S_LEN * KVDIM];
static __device__ __align__(256) __nv_bfloat16 g_Vl[S_LEN * KVDIM];

// ---------------------------------------------------------------------------
// PTX helpers
// ---------------------------------------------------------------------------
__device__ __forceinline__ uint32_t smem_u32(const void* p) {
    uint32_t a;
    asm("{ .reg .u64 t; cvta.to.shared.u64 t, %1; cvt.u32.u64 %0, t; }" : "=r"(a) : "l"(p));
    return a;
}
#define CP_ASYNC16(dst, src) asm volatile("cp.async.cg.shared.global [%0], [%1], 16;" :: "r"(dst), "l"(src))
#define CP_COMMIT()          asm volatile("cp.async.commit_group;" ::: "memory")
#define CP_WAIT(n)           asm volatile("cp.async.wait_group %0;" :: "n"(n) : "memory")

#define LDSM_X4(r0, r1, r2, r3, addr)                                            \
    asm volatile("ldmatrix.sync.aligned.m8n8.x4.shared.b16 {%0,%1,%2,%3}, [%4];" \
        : "=r"(r0), "=r"(r1), "=r"(r2), "=r"(r3) : "r"(addr))

#define LDSM_X4_T(r0, r1, r2, r3, addr)                                                \
    asm volatile("ldmatrix.sync.aligned.m8n8.x4.trans.shared.b16 {%0,%1,%2,%3}, [%4];" \
        : "=r"(r0), "=r"(r1), "=r"(r2), "=r"(r3) : "r"(addr))

__device__ __forceinline__ void mma_bf16(float* c, uint32_t a0, uint32_t a1,
                                         uint32_t a2, uint32_t a3,
                                         uint32_t b0, uint32_t b1) {
    asm volatile(
        "mma.sync.aligned.m16n8k16.row.col.f32.bf16.bf16.f32 "
        "{%0,%1,%2,%3}, {%4,%5,%6,%7}, {%8,%9}, {%0,%1,%2,%3};"
        : "+f"(c[0]), "+f"(c[1]), "+f"(c[2]), "+f"(c[3])
        : "r"(a0), "r"(a1), "r"(a2), "r"(a3), "r"(b0), "r"(b1));
}

// ---------------------------------------------------------------------------
// bf16 HMMA GEMM, segmented over N (up to 3 B/C segments sharing A).
// BM=128, BN=128, BK=64, 3-stage cp.async pipeline, 4 warps, warp tile 64x64.
// ---------------------------------------------------------------------------
#define BM 128
#define BN 128
#define BKE 64
#define ROW_B 144
#define TILE_BYTES (128 * ROW_B)
#define STAGE_BYTES (2 * TILE_BYTES)
#define NSTAGE 3
#define GEMM_SMEM (NSTAGE * STAGE_BYTES)

__device__ __forceinline__ void load_tiles(uint32_t stage_base,
    const __nv_bfloat16* __restrict__ A, const __nv_bfloat16* __restrict__ B,
    int bm, int bn, int kc, int Kp, int tid)
{
    const char* Ag = (const char*)(A + (size_t)bm * Kp + kc * BKE);
    const char* Bg = (const char*)(B + (size_t)bn * Kp + kc * BKE);
    const size_t rowb = (size_t)Kp * 2;
    const uint32_t sA = stage_base;
    const uint32_t sB = stage_base + TILE_BYTES;
#pragma unroll
    for (int i = 0; i < 8; i++) {
        int idx = tid + i * 128;
        int row = idx >> 3, seg = idx & 7;
        CP_ASYNC16(sA + row * ROW_B + seg * 16, Ag + (size_t)row * rowb + seg * 16);
    }
#pragma unroll
    for (int i = 0; i < 8; i++) {
        int idx = tid + i * 128;
        int row = idx >> 3, seg = idx & 7;
        CP_ASYNC16(sB + row * ROW_B + seg * 16, Bg + (size_t)row * rowb + seg * 16);
    }
}

__global__ __launch_bounds__(128) void gemm_mma(
    const __nv_bfloat16* __restrict__ A,
    const __nv_bfloat16* __restrict__ B0, float* __restrict__ C0, int nt0, int N0,
    const __nv_bfloat16* __restrict__ B1, float* __restrict__ C1, int nt1, int N1,
    const __nv_bfloat16* __restrict__ B2, float* __restrict__ C2, int N2,
    int Kp)
{
    extern __shared__ char smem[];
    const uint32_t sbase = smem_u32(smem);
    const int tid  = threadIdx.x;
    const int wid  = tid >> 5;
    const int lane = tid & 31;
    const int bm   = blockIdx.y * BM;
    const int NC   = Kp / BKE;

    int bnt = blockIdx.x;
    const __nv_bfloat16* B;
    float* C; int N;
    if (bnt < nt0)            { B = B0; C = C0; N = N0; }
    else if (bnt < nt0 + nt1) { B = B1; C = C1; N = N1; bnt -= nt0; }
    else                      { B = B2; C = C2; N = N2; bnt -= nt0 + nt1; }
    const int bn = bnt * BN;

    const int wm = (wid >> 1) * 64;
    const int wn = (wid & 1) * 64;

    float acc[4][8][4];
#pragma unroll
    for (int t = 0; t < 4; t++)
#pragma unroll
        for (int j = 0; j < 8; j++)
#pragma unroll
            for (int q = 0; q < 4; q++) acc[t][j][q] = 0.f;

    const int a_row    = ((lane >> 3) & 1) * 8 + (lane & 7);
    const int a_cshift = ((lane >> 4) & 1) * 16;
    const int b_row    = ((lane >> 4) & 1) * 8 + (lane & 7);
    const int b_cshift = ((lane >> 3) & 1) * 16;

    load_tiles(sbase,               A, B, bm, bn, 0, Kp, tid); CP_COMMIT();
    load_tiles(sbase + STAGE_BYTES, A, B, bm, bn, 1, Kp, tid); CP_COMMIT();

    for (int c = 0; c < NC; c++) {
        CP_WAIT(1);
        __syncthreads();

        if (c + 2 < NC)
            load_tiles(sbase + ((c + 2) % NSTAGE) * STAGE_BYTES, A, B, bm, bn, c + 2, Kp, tid);
        CP_COMMIT();

        const uint32_t sA = sbase + (c % NSTAGE) * STAGE_BYTES;
        const uint32_t sB = sA + TILE_BYTES;
#pragma unroll
        for (int ks = 0; ks < 4; ks++) {
            uint32_t a[4][4];
#pragma unroll
            for (int t = 0; t < 4; t++) {
                uint32_t addr = sA + (wm + t * 16 + a_row) * ROW_B + ks * 32 + a_cshift;
                LDSM_X4(a[t][0], a[t][1], a[t][2], a[t][3], addr);
            }
#pragma unroll
            for (int p = 0; p < 4; p++) {
                uint32_t b0, b1, b2, b3;
                uint32_t addr = sB + (wn + p * 16 + b_row) * ROW_B + ks * 32 + b_cshift;
                LDSM_X4(b0, b1, b2, b3, addr);
#pragma unroll
                for (int t = 0; t < 4; t++) {
                    mma_bf16(acc[t][2 * p],     a[t][0], a[t][1], a[t][2], a[t][3], b0, b1);
                    mma_bf16(acc[t][2 * p + 1], a[t][0], a[t][1], a[t][2], a[t][3], b2, b3);
                }
            }
        }
    }

#pragma unroll
    for (int t = 0; t < 4; t++) {
        const int r0 = bm + wm + t * 16 + (lane >> 2);
#pragma unroll
        for (int j = 0; j < 8; j++) {
            const int col = bn + wn + j * 8 + (lane & 3) * 2;
            float* c0 = C + (size_t)r0 * N + col;
            float* c1 = C + (size_t)(r0 + 8) * N + col;
            *(float2*)c0 = make_float2(acc[t][j][0], acc[t][j][1]);
            *(float2*)c1 = make_float2(acc[t][j][2], acc[t][j][3]);
        }
    }
}

// ---------------------------------------------------------------------------
// fp32 -> split bf16 (GEMM operand layout), 2 elements/thread.
// mode 0 (A side): [hi | lo | hi]; mode 1 (B side): [hi | hi | lo]
// ---------------------------------------------------------------------------
__global__ void split_kernel(const float* __restrict__ X, __nv_bfloat16* __restrict__ Y,
                             int totalPairs, int Cpairs, int mode)
{
    int t = blockIdx.x * blockDim.x + threadIdx.x;
    if (t >= totalPairs) return;
    int r = t / Cpairs, c = t - r * Cpairs;
    float2 x = *(const float2*)(X + 2 * (size_t)t);
    __nv_bfloat162 h = __floats2bfloat162_rn(x.x, x.y);
    __nv_bfloat162 l = __floats2bfloat162_rn(x.x - __bfloat162float(h.x),
                                             x.y - __bfloat162float(h.y));
    uint32_t* row = (uint32_t*)(Y + (size_t)r * 6 * Cpairs);
    uint32_t hv = *(uint32_t*)&h, lv = *(uint32_t*)&l;
    if (mode == 0) { row[c] = hv; row[Cpairs + c] = lv; row[2 * Cpairs + c] = hv; }
    else           { row[c] = hv; row[Cpairs + c] = hv; row[2 * Cpairs + c] = lv; }
}

// ---------------------------------------------------------------------------
// Indexed RoPE + hi/lo bf16 split (for flash operands). X: [S, nheads*HD] fp32.
// ---------------------------------------------------------------------------
__global__ void rope_split(const float* __restrict__ X,
                           __nv_bfloat16* __restrict__ Xh, __nv_bfloat16* __restrict__ Xl,
                           const float* __restrict__ cosT, const float* __restrict__ sinT,
                           const int* __restrict__ idx,
                           int nheads, int group, float scale, int total)
{
    int t = blockIdx.x * blockDim.x + threadIdx.x;
    if (t >= total) return;
    int d = t % 48;
    int h = (t / 48) % nheads;
    int s = t / (48 * nheads);
    int hk = h / group;

    const float* base = X + (size_t)s * (nheads * HD) + h * HD;
    float x1 = base[d];
    float x2 = base[d + 48];

    int i1 = idx[hk * HD + d];
    int i2 = idx[hk * HD + d + 48];
    float c1 = cosT[s * DFULL + i1], s1 = sinT[s * DFULL + i1];
    float c2 = cosT[s * DFULL + i2], s2 = sinT[s * DFULL + i2];

    float lo = (x1 * c1 - x2 * s1) * scale;
    float hi = (x2 * c2 + x1 * s2) * scale;

    size_t o = (size_t)s * (nheads * HD) + h * HD;
    __nv_bfloat16 bh = __float2bfloat16(lo);
    Xh[o + d] = bh;
    Xl[o + d] = __float2bfloat16(lo - __bfloat162float(bh));
    bh = __float2bfloat16(hi);
    Xh[o + d + 48] = bh;
    Xl[o + d + 48] = __float2bfloat16(hi - __bfloat162float(bh));
}

// plain hi/lo split (V)
__global__ void split2_kernel(const float* __restrict__ X,
                              __nv_bfloat16* __restrict__ Xh, __nv_bfloat16* __restrict__ Xl,
                              int total)
{
    int t = blockIdx.x * blockDim.x + threadIdx.x;
    if (t >= total) return;
    float x = X[t];
    __nv_bfloat16 h = __float2bfloat16(x);
    Xh[t] = h;
    Xl[t] = __float2bfloat16(x - __bfloat162float(h));
}

// ---------------------------------------------------------------------------
// HMMA flash attention, causal GQA. CTA = 128 q-rows x 1 head, 8 warps.
// 64-key blocks, double-buffered cp.async KV stages.
// 3-term split MMAs: S = QhKh + QlKh + QhKl;  O += PhVh + PlVh + PhVl.
// ---------------------------------------------------------------------------
#define FD   96
#define FBM  128
#define FBN  64
#define FROW 208
#define FQ_BYTES  (FBM * FROW)       // 26624
#define FKV_BYTES (FBN * FROW)       // 13312
#define STG_BYTES (4 * FKV_BYTES)    // 53248
#define FLASH_SMEM (2 * FQ_BYTES + 2 * STG_BYTES)   // 159744

__device__ __forceinline__ void flash_load_kv(uint32_t st_base,
    const __nv_bfloat16* Kh, const __nv_bfloat16* Kl,
    const __nv_bfloat16* Vh, const __nv_bfloat16* Vl,
    int key0, int hk, int tid)
{
    const size_t goff = (size_t)key0 * (KVDIM * 2) + hk * (FD * 2);
    const char* g0 = (const char*)Kh + goff;
    const char* g1 = (const char*)Kl + goff;
    const char* g2 = (const char*)Vh + goff;
    const char* g3 = (const char*)Vl + goff;
#pragma unroll
    for (int i = 0; i < 3; i++) {
        int idx = tid + i * 256;
        int row = idx / 12, seg = idx - row * 12;
        uint32_t d = st_base + row * FROW + seg * 16;
        size_t go = (size_t)row * (KVDIM * 2) + seg * 16;
        CP_ASYNC16(d,                 g0 + go);
        CP_ASYNC16(d +     FKV_BYTES, g1 + go);
        CP_ASYNC16(d + 2 * FKV_BYTES, g2 + go);
        CP_ASYNC16(d + 3 * FKV_BYTES, g3 + go);
    }
}

__global__ __launch_bounds__(256, 1) void flash_mma(
    const __nv_bfloat16* __restrict__ Qh, const __nv_bfloat16* __restrict__ Ql,
    const __nv_bfloat16* __restrict__ Kh, const __nv_bfloat16* __restrict__ Kl,
    const __nv_bfloat16* __restrict__ Vh, const __nv_bfloat16* __restrict__ Vl,
    float* __restrict__ O)
{
    extern __shared__ char smem[];
    const uint32_t sb = smem_u32(smem);
    const int tid = threadIdx.x, wid = tid >> 5, lane = tid & 31;
    const int h = blockIdx.y, hk = h / GROUPS;
    const int qbase = ((int)gridDim.x - 1 - (int)blockIdx.x) * FBM;  // heavy first
    const int nb = qbase / FBN + 2;

    const uint32_t sQh_ = sb, sQl_ = sb + FQ_BYTES;
    const uint32_t st0 = sb + 2 * FQ_BYTES;

    // Q tiles + KV stage0
    {
        const char* gqh = (const char*)(Qh + (size_t)qbase * QDIM + h * FD);
        const char* gql = (const char*)(Ql + (size_t)qbase * QDIM + h * FD);
#pragma unroll
        for (int i = 0; i < 6; i++) {
            int idx = tid + i * 256;
            int row = idx / 12, seg = idx - row * 12;
            uint32_t d = row * FROW + seg * 16;
            size_t go = (size_t)row * (QDIM * 2) + seg * 16;
            CP_ASYNC16(sQh_ + d, gqh + go);
            CP_ASYNC16(sQl_ + d, gql + go);
        }
        flash_load_kv(st0, Kh, Kl, Vh, Vl, 0, hk, tid);
        CP_COMMIT();
    }

    float oacc[12][4];
#pragma unroll
    for (int j = 0; j < 12; j++)
#pragma unroll
        for (int q = 0; q < 4; q++) oacc[j][q] = 0.f;
    float m0 = -CUDART_INF_F, m1 = -CUDART_INF_F, l0 = 0.f, l1 = 0.f;

    const int a_row = (lane & 7) + ((lane >> 3) & 1) * 8;
    const int a_cs  = ((lane >> 4) & 1) * 16;
    const int b_row = (lane & 7) + ((lane >> 4) & 1) * 8;
    const int b_cs  = ((lane >> 3) & 1) * 16;
    const int t_row = (lane & 7) + ((lane >> 3) & 1) * 8;   // trans-V rows (keys)
    const int t_cs  = ((lane >> 4) & 1) * 16;               // trans-V dim shift

    const int qr_lo = qbase + wid * 16;
    const int row0  = qr_lo + (lane >> 2);

    for (int kb = 0; kb < nb; kb++) {
        if (kb + 1 < nb) {
            flash_load_kv(st0 + ((kb + 1) & 1) * STG_BYTES, Kh, Kl, Vh, Vl,
                          (kb + 1) * FBN, hk, tid);
            CP_COMMIT();
            CP_WAIT(1);
        } else {
            CP_WAIT(0);
        }
        __syncthreads();

        const int key0 = kb * FBN;
        if (key0 <= qr_lo + 15) {
            const uint32_t sKh_ = st0 + (kb & 1) * STG_BYTES;
            const uint32_t sKl_ = sKh_ + FKV_BYTES;
            const uint32_t sVh_ = sKh_ + 2 * FKV_BYTES;
            const uint32_t sVl_ = sKh_ + 3 * FKV_BYTES;

            float sacc[8][4];
#pragma unroll
            for (int j = 0; j < 8; j++)
#pragma unroll
                for (int q = 0; q < 4; q++) sacc[j][q] = 0.f;

            // S = Qh*Kh + Ql*Kh + Qh*Kl
#pragma unroll
            for (int pass = 0; pass < 3; pass++) {
                const uint32_t sa = (pass == 1) ? sQl_ : sQh_;
                const uint32_t sk = (pass == 2) ? sKl_ : sKh_;
#pragma unroll
                for (int ks = 0; ks < 6; ks++) {
                    uint32_t a0, a1, a2, a3;
                    LDSM_X4(a0, a1, a2, a3,
                            sa + (wid * 16 + a_row) * FROW + ks * 32 + a_cs);
#pragma unroll
                    for (int p = 0; p < 4; p++) {
                        uint32_t b0, b1, b2, b3;
                        LDSM_X4(b0, b1, b2, b3,
                                sk + (p * 16 + b_row) * FROW + ks * 32 + b_cs);
                        mma_bf16(sacc[2 * p],     a0, a1, a2, a3, b0, b1);
                        mma_bf16(sacc[2 * p + 1], a0, a1, a2, a3, b2, b3);
                    }
                }
            }

            // causal mask (only near-diagonal blocks need it)
            if (key0 + FBN - 1 > qr_lo) {
#pragma unroll
                for (int j = 0; j < 8; j++) {
                    int kcol = key0 + 8 * j + (lane & 3) * 2;
                    if (kcol     > row0)     sacc[j][0] = -CUDART_INF_F;
                    if (kcol + 1 > row0)     sacc[j][1] = -CUDART_INF_F;
                    if (kcol     > row0 + 8) sacc[j][2] = -CUDART_INF_F;
                    if (kcol + 1 > row0 + 8) sacc[j][3] = -CUDART_INF_F;
                }
            }

            // online softmax
            float mx0 = sacc[0][0], mx1 = sacc[0][2];
#pragma unroll
            for (int j = 0; j < 8; j++) {
                mx0 = fmaxf(mx0, fmaxf(sacc[j][0], sacc[j][1]));
                mx1 = fmaxf(mx1, fmaxf(sacc[j][2], sacc[j][3]));
            }
            mx0 = fmaxf(mx0, __shfl_xor_sync(0xffffffffu, mx0, 1));
            mx0 = fmaxf(mx0, __shfl_xor_sync(0xffffffffu, mx0, 2));
            mx1 = fmaxf(mx1, __shfl_xor_sync(0xffffffffu, mx1, 1));
            mx1 = fmaxf(mx1, __shfl_xor_sync(0xffffffffu, mx1, 2));

            float mn0 = fmaxf(m0, mx0), mn1 = fmaxf(m1, mx1);
            float al0 = __expf(m0 - mn0), al1 = __expf(m1 - mn1);

            uint32_t ph[8][2], pl[8][2];
            float sum0 = 0.f, sum1 = 0.f;
#pragma unroll
            for (int j = 0; j < 8; j++) {
                float p0 = __expf(sacc[j][0] - mn0), p1 = __expf(sacc[j][1] - mn0);
                float p2 = __expf(sacc[j][2] - mn1), p3 = __expf(sacc[j][3] - mn1);
                sum0 += p0 + p1; sum1 += p2 + p3;
                __nv_bfloat162 h01 = __floats2bfloat162_rn(p0, p1);
                __nv_bfloat162 h23 = __floats2bfloat162_rn(p2, p3);
                ph[j][0] = *(uint32_t*)&h01;
                ph[j][1] = *(uint32_t*)&h23;
                __nv_bfloat162 l01 = __floats2bfloat162_rn(p0 - __bfloat162float(h01.x),
                                                           p1 - __bfloat162float(h01.y));
                __nv_bfloat162 l23 = __floats2bfloat162_rn(p2 - __bfloat162float(h23.x),
                                                           p3 - __bfloat162float(h23.y));
                pl[j][0] = *(uint32_t*)&l01;
                pl[j][1] = *(uint32_t*)&l23;
            }
            sum0 += __shfl_xor_sync(0xffffffffu, sum0, 1);
            sum0 += __shfl_xor_sync(0xffffffffu, sum0, 2);
            sum1 += __shfl_xor_sync(0xffffffffu, sum1, 1);
            sum1 += __shfl_xor_sync(0xffffffffu, sum1, 2);

            l0 = l0 * al0 + sum0;  l1 = l1 * al1 + sum1;
            m0 = mn0;              m1 = mn1;
#pragma unroll
            for (int j = 0; j < 12; j++) {
                oacc[j][0] *= al0; oacc[j][1] *= al0;
                oacc[j][2] *= al1; oacc[j][3] *= al1;
            }

            // O += Ph*Vh + Pl*Vh + Ph*Vl
#pragma unroll
            for (int kk = 0; kk < 4; kk++) {
                uint32_t a0 = ph[2 * kk][0], a1 = ph[2 * kk][1];
                uint32_t a2 = ph[2 * kk + 1][0], a3 = ph[2 * kk + 1][1];
                uint32_t c0 = pl[2 * kk][0], c1 = pl[2 * kk][1];
                uint32_t c2 = pl[2 * kk + 1][0], c3 = pl[2 * kk + 1][1];
#pragma unroll
                for (int p = 0; p < 6; p++) {
                    uint32_t vaddr = (16 * kk + t_row) * FROW + p * 32 + t_cs;
                    uint32_t b0, b1, b2, b3;
                    LDSM_X4_T(b0, b1, b2, b3, sVh_ + vaddr);
                    mma_bf16(oacc[2 * p],     a0, a1, a2, a3, b0, b1);
                    mma_bf16(oacc[2 * p + 1], a0, a1, a2, a3, b2, b3);
                    mma_bf16(oacc[2 * p],     c0, c1, c2, c3, b0, b1);
                    mma_bf16(oacc[2 * p + 1], c0, c1, c2, c3, b2, b3);
                    LDSM_X4_T(b0, b1, b2, b3, sVl_ + vaddr);
                    mma_bf16(oacc[2 * p],     a0, a1, a2, a3, b0, b1);
                    mma_bf16(oacc[2 * p + 1], a0, a1, a2, a3, b2, b3);
                }
            }
        }
        __syncthreads();
    }

    const float inv0 = 1.f / l0, inv1 = 1.f / l1;
    float* ob = O + (size_t)row0 * QDIM + h * FD + (lane & 3) * 2;
#pragma unroll
    for (int j = 0; j < 12; j++) {
        *(float2*)(ob + j * 8)            = make_float2(oacc[j][0] * inv0, oacc[j][1] * inv0);
        *(float2*)(ob + 8 * QDIM + j * 8) = make_float2(oacc[j][2] * inv1, oacc[j][3] * inv1);
    }
}

// ---------------------------------------------------------------------------
extern "C" void kernel_launch(void* const* d_in, const int* in_sizes, int n_in,
                              void* d_out, int out_size)
{
    const float* hs  = (const float*)d_in[0];
    const float* cs  = (const float*)d_in[1];
    const float* sn  = (const float*)d_in[2];
    const int*   idx = (const int*)  d_in[3];
    const float* Wq  = (const float*)d_in[4];
    const float* Wk  = (const float*)d_in[5];
    const float* Wv  = (const float*)d_in[6];
    const float* Wo  = (const float*)d_in[7];
    float* out = (float*)d_out;

    float *Qb, *Kb, *Vb, *AOb;
    __nv_bfloat16 *hsb, *wqb, *wkb, *wvb, *aob, *wob;
    __nv_bfloat16 *qh, *ql, *kh, *kl, *vh, *vl;
    cudaGetSymbolAddress((void**)&Qb,  g_Q);
    cudaGetSymbolAddress((void**)&Kb,  g_K);
    cudaGetSymbolAddress((void**)&Vb,  g_V);
    cudaGetSymbolAddress((void**)&AOb, g_AO);
    cudaGetSymbolAddress((void**)&hsb, g_hsb);
    cudaGetSymbolAddress((void**)&wqb, g_wqb);
    cudaGetSymbolAddress((void**)&wkb, g_wkb);
    cudaGetSymbolAddress((void**)&wvb, g_wvb);
    cudaGetSymbolAddress((void**)&aob, g_aob);
    cudaGetSymbolAddress((void**)&wob, g_wob);
    cudaGetSymbolAddress((void**)&qh,  g_Qh);
    cudaGetSymbolAddress((void**)&ql,  g_Ql);
    cudaGetSymbolAddress((void**)&kh,  g_Kh);
    cudaGetSymbolAddress((void**)&kl,  g_Kl);
    cudaGetSymbolAddress((void**)&vh,  g_Vh);
    cudaGetSymbolAddress((void**)&vl,  g_Vl);

    static bool attr_set = false;
    if (!attr_set) {
        cudaFuncSetAttribute(gemm_mma,  cudaFuncAttributeMaxDynamicSharedMemorySize, GEMM_SMEM);
        cudaFuncSetAttribute(flash_mma, cudaFuncAttributeMaxDynamicSharedMemorySize, FLASH_SMEM);
        attr_set = true;
    }

    // split fp32 -> [hi|lo|hi] / [hi|hi|lo] bf16 (GEMM operands)
    {
        int t;
        t = S_LEN * HIDDEN / 2; split_kernel<<<(t + 255) / 256, 256>>>(hs, hsb, t, HIDDEN / 2, 0);
        t = QDIM  * HIDDEN / 2; split_kernel<<<(t + 255) / 256, 256>>>(Wq, wqb, t, HIDDEN / 2, 1);
        t = KVDIM * HIDDEN / 2; split_kernel<<<(t + 255) / 256, 256>>>(Wk, wkb, t, HIDDEN / 2, 1);
        t = KVDIM * HIDDEN / 2; split_kernel<<<(t + 255) / 256, 256>>>(Wv, wvb, t, HIDDEN / 2, 1);
        t = HIDDEN * QDIM  / 2; split_kernel<<<(t + 255) / 256, 256>>>(Wo, wob, t, QDIM / 2,   1);
    }

    // fused QKV projection
    gemm_mma<<<dim3(36, S_LEN / BM), 128, GEMM_SMEM>>>(
        hsb,
        wqb, Qb, QDIM / BN,  QDIM,
        wkb, Kb, KVDIM / BN, KVDIM,
        wvb, Vb,             KVDIM,
        KP_QKV);

    // RoPE + hi/lo split for flash operands (Q pre-scaled by 1/sqrt(128))
    const int totQ = S_LEN * NH  * 48;
    const int totK = S_LEN * NKV * 48;
    rope_split<<<(totQ + 255) / 256, 256>>>(Qb, qh, ql, cs, sn, idx, NH,  GROUPS, ATT_SCALE, totQ);
    rope_split<<<(totK + 255) / 256, 256>>>(Kb, kh, kl, cs, sn, idx, NKV, 1,      1.0f,      totK);
    {
        int t = S_LEN * KVDIM;
        split2_kernel<<<(t + 255) / 256, 256>>>(Vb, vh, vl, t);
    }

    // causal GQA attention (HMMA)
    flash_mma<<<dim3(S_LEN / FBM, NH), 256, FLASH_SMEM>>>(qh, ql, kh, kl, vh, vl, AOb);

    // split attention output, then output projection -> d_out
    {
        int t = S_LEN * QDIM / 2;
        split_kernel<<<(t + 255) / 256, 256>>>(AOb, aob, t, QDIM / 2, 0);
    }
    gemm_mma<<<dim3(HIDDEN / BN, S_LEN / BM), 128, GEMM_SMEM>>>(
        aob,
        wob, out, HIDDEN / BN, HIDDEN,
        wob, out, 0,           HIDDEN,
        wob, out,              HIDDEN,
        KP_O);
}